// round 1
// baseline (speedup 1.0000x reference)
#include <cuda_runtime.h>
#include <cuda_bf16.h>
#include <math.h>

#define T_DIM 128
#define B_DIM 512
#define N_DIM 256
#define M_DIM 512
#define G_DIM 2048   // 4*M
#define K_GATES 768  // N + M

// ---------------- device scratch (no allocation allowed) ----------------
__device__ float g_UeX[B_DIM * T_DIM * N_DIM];      // [b][s][n]  67 MB
__device__ float g_h[B_DIM * M_DIM];
__device__ float g_c[B_DIM * M_DIM];
__device__ float g_hseq[T_DIM * B_DIM * M_DIM];     // 134 MB
__device__ float g_xt[B_DIM * N_DIM];               // x_tilde
__device__ float g_gates[B_DIM * G_DIM];            // 4 MB
__device__ float g_tmp[(T_DIM * B_DIM) * M_DIM];    // tanh(H@Ud^T)*vd  134 MB
__device__ float g_l[B_DIM * T_DIM];                // attention logits l

// ---------------- init h,c ----------------
__global__ void k_init(const float* __restrict__ h0, const float* __restrict__ c0) {
    int idx = blockIdx.x * blockDim.x + threadIdx.x;
    g_h[idx] = h0[idx];
    g_c[idx] = c0[idx];
}

// ---------------- Ue_x[b][s][n] = sum_t x[t,b,n]*Ue_w[s,t] + Ue_b[s] ----------------
// grid (B, N/64), 256 threads
__global__ void k_ue(const float* __restrict__ x, const float* __restrict__ Ue_w,
                     const float* __restrict__ Ue_b) {
    __shared__ float xs[T_DIM][64];
    int b = blockIdx.x;
    int n0 = blockIdx.y * 64;
    int tid = threadIdx.x;
    for (int idx = tid; idx < T_DIM * 64; idx += 256) {
        int t = idx >> 6, n = idx & 63;
        xs[t][n] = x[(size_t)t * B_DIM * N_DIM + b * N_DIM + n0 + n];
    }
    __syncthreads();
    // 8192 outputs (s,n), 32 per thread; lanes share s, n = tid&63 varies -> coalesced writes
    for (int r = 0; r < 32; r++) {
        int o = tid + 256 * r;
        int s = o >> 6, n = o & 63;
        float acc = Ue_b[s];
        const float* uw = Ue_w + s * T_DIM;
        #pragma unroll 8
        for (int t = 0; t < T_DIM; t++) acc += xs[t][n] * uw[t];
        g_UeX[(b * T_DIM + s) * N_DIM + n0 + n] = acc;
    }
}

// ---------------- per-step encoder input attention ----------------
// grid 64 (8 batch rows per block), 256 threads
__global__ void k_attn(int t, const float* __restrict__ x,
                       const float* __restrict__ We_w, const float* __restrict__ We_b,
                       const float* __restrict__ ve_w, const float* __restrict__ ve_b) {
    __shared__ float s_hc[8][1024];
    __shared__ float s_we[8][T_DIM];
    __shared__ float s_e[8][N_DIM];
    __shared__ float s_ve[T_DIM];
    int tid = threadIdx.x;
    int lane = tid & 31;
    int w = tid >> 5;
    int b0 = blockIdx.x * 8;

    for (int idx = tid; idx < 8 * 1024; idx += 256) {
        int bb = idx >> 10, j = idx & 1023;
        s_hc[bb][j] = (j < M_DIM) ? g_h[(b0 + bb) * M_DIM + j]
                                  : g_c[(b0 + bb) * M_DIM + (j - M_DIM)];
    }
    if (tid < T_DIM) s_ve[tid] = ve_w[tid];
    __syncthreads();

    // phase 1: we[bb][s], warp w handles s in [16w,16w+16); We_w read once per block
    for (int s = w * 16; s < w * 16 + 16; s++) {
        float acc[8] = {0, 0, 0, 0, 0, 0, 0, 0};
        const float* Wr = We_w + s * 1024;
        for (int k = lane; k < 1024; k += 32) {
            float wv = Wr[k];
            #pragma unroll
            for (int bb = 0; bb < 8; bb++) acc[bb] += s_hc[bb][k] * wv;
        }
        #pragma unroll
        for (int bb = 0; bb < 8; bb++) {
            float v = acc[bb];
            #pragma unroll
            for (int o = 16; o; o >>= 1) v += __shfl_xor_sync(0xffffffffu, v, o);
            if (lane == 0) s_we[bb][s] = v + We_b[s];
        }
    }
    __syncthreads();

    // phase 2: e[bb][n] = sum_s tanh(we + UeX)*ve  (coalesced UeX reads, n = tid)
    float ve_b0 = ve_b[0];
    for (int bb = 0; bb < 8; bb++) {
        int b = b0 + bb;
        int n = tid;
        float acc = 0.0f;
        const float* ue = g_UeX + (size_t)b * T_DIM * N_DIM + n;
        #pragma unroll 4
        for (int s = 0; s < T_DIM; s++)
            acc += tanhf(s_we[bb][s] + ue[(size_t)s * N_DIM]) * s_ve[s];
        s_e[bb][n] = acc + ve_b0;
    }
    __syncthreads();

    // phase 3: softmax over n (warp w -> batch row w), then x_tilde = alpha * x[t]
    {
        int bb = w;
        int b = b0 + bb;
        float ev[8];
        float m = -1e30f;
        #pragma unroll
        for (int u = 0; u < 8; u++) { ev[u] = s_e[bb][lane + 32 * u]; m = fmaxf(m, ev[u]); }
        #pragma unroll
        for (int o = 16; o; o >>= 1) m = fmaxf(m, __shfl_xor_sync(0xffffffffu, m, o));
        float sum = 0.0f;
        #pragma unroll
        for (int u = 0; u < 8; u++) { ev[u] = expf(ev[u] - m); sum += ev[u]; }
        #pragma unroll
        for (int o = 16; o; o >>= 1) sum += __shfl_xor_sync(0xffffffffu, sum, o);
        float inv = 1.0f / sum;
        const float* xt = x + (size_t)t * B_DIM * N_DIM + b * N_DIM;
        #pragma unroll
        for (int u = 0; u < 8; u++) {
            int n = lane + 32 * u;
            g_xt[b * N_DIM + n] = ev[u] * inv * xt[n];
        }
    }
}

// ---------------- gates = [x_tilde|h] @ [Wih|Whh]^T + b_ih + b_hh ----------------
// C: 512x2048, K=768. 64x64 tile, BK=16, 256 thr, 4x4 microtile. grid (32, 8)
__global__ void k_gates(const float* __restrict__ Wih, const float* __restrict__ Whh,
                        const float* __restrict__ b_ih, const float* __restrict__ b_hh) {
    __shared__ float As[16][68];
    __shared__ float Bs[16][68];
    int cb = blockIdx.x, rb = blockIdx.y;
    int tid = threadIdx.x;
    int tx = tid & 15, ty = tid >> 4;
    int kl = tid & 15, il = tid >> 4;
    int row0 = rb * 64, col0 = cb * 64;
    float acc[4][4] = {};
    for (int k0 = 0; k0 < K_GATES; k0 += 16) {
        int k = k0 + kl;
        #pragma unroll
        for (int s = 0; s < 4; s++) {
            int i = il + s * 16;
            int row = row0 + i;
            As[kl][i] = (k < N_DIM) ? g_xt[row * N_DIM + k] : g_h[row * M_DIM + (k - N_DIM)];
            int j = col0 + i;
            Bs[kl][i] = (k < N_DIM) ? Wih[j * N_DIM + k] : Whh[j * M_DIM + (k - N_DIM)];
        }
        __syncthreads();
        #pragma unroll
        for (int kk = 0; kk < 16; kk++) {
            float4 a4 = *(const float4*)&As[kk][ty * 4];
            float4 b4 = *(const float4*)&Bs[kk][tx * 4];
            float av[4] = {a4.x, a4.y, a4.z, a4.w};
            float bv[4] = {b4.x, b4.y, b4.z, b4.w};
            #pragma unroll
            for (int ii = 0; ii < 4; ii++)
                #pragma unroll
                for (int jj = 0; jj < 4; jj++) acc[ii][jj] += av[ii] * bv[jj];
        }
        __syncthreads();
    }
    #pragma unroll
    for (int ii = 0; ii < 4; ii++) {
        int row = row0 + ty * 4 + ii;
        #pragma unroll
        for (int jj = 0; jj < 4; jj++) {
            int j = col0 + tx * 4 + jj;
            g_gates[row * G_DIM + j] = acc[ii][jj] + b_ih[j] + b_hh[j];
        }
    }
}

// ---------------- LSTM cell ----------------
__global__ void k_cell(int t) {
    int b = blockIdx.x;
    int m = threadIdx.x;
    const float* gr = g_gates + b * G_DIM;
    float ig = gr[m];
    float fg = gr[M_DIM + m];
    float gg = gr[2 * M_DIM + m];
    float og = gr[3 * M_DIM + m];
    float si = 1.0f / (1.0f + expf(-ig));
    float sf = 1.0f / (1.0f + expf(-fg));
    float so = 1.0f / (1.0f + expf(-og));
    float cn = sf * g_c[b * M_DIM + m] + si * tanhf(gg);
    float hn = so * tanhf(cn);
    g_c[b * M_DIM + m] = cn;
    g_h[b * M_DIM + m] = hn;
    g_hseq[(size_t)t * B_DIM * M_DIM + b * M_DIM + m] = hn;
}

// ---------------- final: tmp[r][j] = tanh(H[r]@Ud[j] + Ud_b[j]) * vd_w[j] ----------------
// rows r = t*B + b over T*B=65536; K=512. grid (8, 1024)
__global__ void k_ud(const float* __restrict__ Ud_w, const float* __restrict__ Ud_b,
                     const float* __restrict__ vd_w) {
    __shared__ float As[16][68];
    __shared__ float Bs[16][68];
    int cb = blockIdx.x, rb = blockIdx.y;
    int tid = threadIdx.x;
    int tx = tid & 15, ty = tid >> 4;
    int kl = tid & 15, il = tid >> 4;
    int row0 = rb * 64, col0 = cb * 64;
    float acc[4][4] = {};
    for (int k0 = 0; k0 < M_DIM; k0 += 16) {
        int k = k0 + kl;
        #pragma unroll
        for (int s = 0; s < 4; s++) {
            int i = il + s * 16;
            As[kl][i] = g_hseq[(size_t)(row0 + i) * M_DIM + k];
            Bs[kl][i] = Ud_w[(col0 + i) * M_DIM + k];
        }
        __syncthreads();
        #pragma unroll
        for (int kk = 0; kk < 16; kk++) {
            float4 a4 = *(const float4*)&As[kk][ty * 4];
            float4 b4 = *(const float4*)&Bs[kk][tx * 4];
            float av[4] = {a4.x, a4.y, a4.z, a4.w};
            float bv[4] = {b4.x, b4.y, b4.z, b4.w};
            #pragma unroll
            for (int ii = 0; ii < 4; ii++)
                #pragma unroll
                for (int jj = 0; jj < 4; jj++) acc[ii][jj] += av[ii] * bv[jj];
        }
        __syncthreads();
    }
    #pragma unroll
    for (int ii = 0; ii < 4; ii++) {
        int row = row0 + ty * 4 + ii;
        #pragma unroll
        for (int jj = 0; jj < 4; jj++) {
            int j = col0 + tx * 4 + jj;
            g_tmp[(size_t)row * M_DIM + j] = tanhf(acc[ii][jj] + Ud_b[j]) * vd_w[j];
        }
    }
}

// ---------------- l[b][t] = sum_j tmp[r][j] + vd_b ----------------
__global__ void k_lred(const float* __restrict__ vd_b) {
    __shared__ float red[4];
    int r = blockIdx.x;
    int tid = threadIdx.x;  // 128
    const float4* p = (const float4*)(g_tmp + (size_t)r * M_DIM);
    float4 v = p[tid];
    float s = v.x + v.y + v.z + v.w;
    #pragma unroll
    for (int o = 16; o; o >>= 1) s += __shfl_xor_sync(0xffffffffu, s, o);
    if ((tid & 31) == 0) red[tid >> 5] = s;
    __syncthreads();
    if (tid == 0) {
        float tot = red[0] + red[1] + red[2] + red[3] + vd_b[0];
        int tt = r >> 9;      // r / 512
        int b = r & 511;      // r % 512
        g_l[b * T_DIM + tt] = tot;
    }
}

// ---------------- beta = softmax_t(l), written to d_out[512 + b*128 + t] ----------------
__global__ void k_beta(float* __restrict__ out) {
    __shared__ float red[128];
    int b = blockIdx.x;
    int tid = threadIdx.x;  // 128
    float v = g_l[b * T_DIM + tid];
    red[tid] = v;
    __syncthreads();
    for (int o = 64; o; o >>= 1) { if (tid < o) red[tid] = fmaxf(red[tid], red[tid + o]); __syncthreads(); }
    float mx = red[0];
    __syncthreads();
    float e = expf(v - mx);
    red[tid] = e;
    __syncthreads();
    for (int o = 64; o; o >>= 1) { if (tid < o) red[tid] += red[tid + o]; __syncthreads(); }
    out[B_DIM + b * T_DIM + tid] = e / red[0];
}

// ---------------- ctx + logits fused ----------------
__global__ void k_out(float* __restrict__ out, const float* __restrict__ out_w,
                      const float* __restrict__ out_b) {
    __shared__ float s_beta[T_DIM];
    __shared__ float red[512];
    int b = blockIdx.x;
    int tid = threadIdx.x;  // 512
    if (tid < T_DIM) s_beta[tid] = out[B_DIM + b * T_DIM + tid];
    __syncthreads();
    float acc = 0.0f;
    #pragma unroll 4
    for (int tt = 0; tt < T_DIM; tt++)
        acc += s_beta[tt] * g_hseq[(size_t)tt * B_DIM * M_DIM + b * M_DIM + tid];
    red[tid] = acc * out_w[tid];
    __syncthreads();
    for (int o = 256; o; o >>= 1) { if (tid < o) red[tid] += red[tid + o]; __syncthreads(); }
    if (tid == 0) out[b] = red[0] + out_b[0];
}

// ---------------- host launcher ----------------
extern "C" void kernel_launch(void* const* d_in, const int* in_sizes, int n_in,
                              void* d_out, int out_size) {
    const float* x    = (const float*)d_in[0];
    const float* h0   = (const float*)d_in[1];
    const float* c0   = (const float*)d_in[2];
    const float* Wih  = (const float*)d_in[3];
    const float* Whh  = (const float*)d_in[4];
    const float* b_ih = (const float*)d_in[5];
    const float* b_hh = (const float*)d_in[6];
    const float* We_w = (const float*)d_in[7];
    const float* We_b = (const float*)d_in[8];
    const float* Ue_w = (const float*)d_in[9];
    const float* Ue_b = (const float*)d_in[10];
    const float* ve_w = (const float*)d_in[11];
    const float* ve_b = (const float*)d_in[12];
    const float* Ud_w = (const float*)d_in[13];
    const float* Ud_b = (const float*)d_in[14];
    const float* vd_w = (const float*)d_in[15];
    const float* vd_b = (const float*)d_in[16];
    const float* out_w = (const float*)d_in[17];
    const float* out_b = (const float*)d_in[18];
    float* out = (float*)d_out;

    k_init<<<B_DIM, M_DIM>>>(h0, c0);
    k_ue<<<dim3(B_DIM, N_DIM / 64), 256>>>(x, Ue_w, Ue_b);
    for (int t = 0; t < T_DIM; t++) {
        k_attn<<<B_DIM / 8, 256>>>(t, x, We_w, We_b, ve_w, ve_b);
        k_gates<<<dim3(G_DIM / 64, B_DIM / 64), 256>>>(Wih, Whh, b_ih, b_hh);
        k_cell<<<B_DIM, M_DIM>>>(t);
    }
    k_ud<<<dim3(M_DIM / 64, (T_DIM * B_DIM) / 64), 256>>>(Ud_w, Ud_b, vd_w);
    k_lred<<<T_DIM * B_DIM, 128>>>(vd_b);
    k_beta<<<B_DIM, T_DIM>>>(out);
    k_out<<<B_DIM, M_DIM>>>(out, out_w, out_b);
}

// round 2
// speedup vs baseline: 1.1319x; 1.1319x over previous
#include <cuda_runtime.h>
#include <cuda_bf16.h>
#include <math.h>

#define T_DIM 128
#define B_DIM 512
#define N_DIM 256
#define M_DIM 512
#define G_DIM 2048   // 4*M
#define K_GATES 768  // N + M

// ---------------- device scratch (no allocation allowed) ----------------
__device__ float g_UeX[B_DIM * T_DIM * N_DIM];      // [b][s][n]  67 MB
__device__ float g_h[B_DIM * M_DIM];
__device__ float g_c[B_DIM * M_DIM];
__device__ float g_hseq[T_DIM * B_DIM * M_DIM];     // 134 MB
__device__ float g_xt[B_DIM * N_DIM];               // x_tilde
__device__ float g_gates[B_DIM * G_DIM];            // 4 MB
__device__ float g_we[B_DIM * T_DIM];               // per-step we
__device__ float g_part[(T_DIM * B_DIM) * 8];       // per-colblock row sums (2 MB)
__device__ float g_l[B_DIM * T_DIM];                // attention logits l

// ---------------- fast math helpers ----------------
__device__ __forceinline__ float tanh_fast(float x) {
    float y;
    asm("tanh.approx.f32 %0, %1;" : "=f"(y) : "f"(x));
    return y;
}
__device__ __forceinline__ float sigmoid_fast(float x) {
    return 0.5f * tanh_fast(0.5f * x) + 0.5f;
}

// ---------------- init h,c ----------------
__global__ void k_init(const float* __restrict__ h0, const float* __restrict__ c0) {
    int idx = blockIdx.x * blockDim.x + threadIdx.x;
    g_h[idx] = h0[idx];
    g_c[idx] = c0[idx];
}

// ---------------- Ue_x[b][s][n] = sum_t x[t,b,n]*Ue_w[s,t] + Ue_b[s] ----------------
__global__ void k_ue(const float* __restrict__ x, const float* __restrict__ Ue_w,
                     const float* __restrict__ Ue_b) {
    __shared__ float xs[T_DIM][64];
    int b = blockIdx.x;
    int n0 = blockIdx.y * 64;
    int tid = threadIdx.x;
    for (int idx = tid; idx < T_DIM * 64; idx += 256) {
        int t = idx >> 6, n = idx & 63;
        xs[t][n] = x[(size_t)t * B_DIM * N_DIM + b * N_DIM + n0 + n];
    }
    __syncthreads();
    for (int r = 0; r < 32; r++) {
        int o = tid + 256 * r;
        int s = o >> 6, n = o & 63;
        float acc = Ue_b[s];
        const float* uw = Ue_w + s * T_DIM;
        #pragma unroll 8
        for (int t = 0; t < T_DIM; t++) acc += xs[t][n] * uw[t];
        g_UeX[(b * T_DIM + s) * N_DIM + n0 + n] = acc;
    }
}

// ---------------- k_we: fold previous cell + compute we = [h|c]@We_w^T + We_b ----
// grid 128 (4 batch rows/block), 256 threads
__global__ void k_we(int t, const float* __restrict__ We_w, const float* __restrict__ We_b) {
    __shared__ float s_hc[4][1024];
    int tid = threadIdx.x;
    int lane = tid & 31;
    int w = tid >> 5;            // 8 warps
    int b0 = blockIdx.x * 4;

    if (t == 0) {
        for (int idx = tid; idx < 4 * 1024; idx += 256) {
            int bb = idx >> 10, j = idx & 1023;
            s_hc[bb][j] = (j < M_DIM) ? g_h[(b0 + bb) * M_DIM + j]
                                      : g_c[(b0 + bb) * M_DIM + (j - M_DIM)];
        }
    } else {
        // LSTM cell for step t-1: consumes g_gates (from step t-1), updates h,c
        for (int idx = tid; idx < 4 * M_DIM; idx += 256) {
            int bb = idx >> 9, m = idx & 511;
            int b = b0 + bb;
            const float* gr = g_gates + b * G_DIM;
            float si = sigmoid_fast(gr[m]);
            float sf = sigmoid_fast(gr[M_DIM + m]);
            float tg = tanh_fast(gr[2 * M_DIM + m]);
            float so = sigmoid_fast(gr[3 * M_DIM + m]);
            float cn = sf * g_c[b * M_DIM + m] + si * tg;
            float hn = so * tanh_fast(cn);
            g_c[b * M_DIM + m] = cn;
            g_h[b * M_DIM + m] = hn;
            g_hseq[(size_t)(t - 1) * B_DIM * M_DIM + b * M_DIM + m] = hn;
            s_hc[bb][m] = hn;
            s_hc[bb][M_DIM + m] = cn;
        }
    }
    __syncthreads();

    // we[bb][s]: warp w handles s in [16w, 16w+16)
    for (int s = w * 16; s < w * 16 + 16; s++) {
        float acc0 = 0.f, acc1 = 0.f, acc2 = 0.f, acc3 = 0.f;
        const float* Wr = We_w + s * 1024;
        #pragma unroll 4
        for (int k = lane; k < 1024; k += 32) {
            float wv = Wr[k];
            acc0 += s_hc[0][k] * wv;
            acc1 += s_hc[1][k] * wv;
            acc2 += s_hc[2][k] * wv;
            acc3 += s_hc[3][k] * wv;
        }
        #pragma unroll
        for (int o = 16; o; o >>= 1) {
            acc0 += __shfl_xor_sync(0xffffffffu, acc0, o);
            acc1 += __shfl_xor_sync(0xffffffffu, acc1, o);
            acc2 += __shfl_xor_sync(0xffffffffu, acc2, o);
            acc3 += __shfl_xor_sync(0xffffffffu, acc3, o);
        }
        if (lane == 0) {
            float bb_ = We_b[s];
            g_we[(b0 + 0) * T_DIM + s] = acc0 + bb_;
            g_we[(b0 + 1) * T_DIM + s] = acc1 + bb_;
            g_we[(b0 + 2) * T_DIM + s] = acc2 + bb_;
            g_we[(b0 + 3) * T_DIM + s] = acc3 + bb_;
        }
    }
}

// ---------------- k_e: e -> softmax -> x_tilde. grid 512 (1 batch/block), 256 thr ----
__global__ void k_e(int t, const float* __restrict__ x,
                    const float* __restrict__ ve_w, const float* __restrict__ ve_b) {
    __shared__ float s_we[T_DIM];
    __shared__ float s_ve[T_DIM];
    __shared__ float red[256];
    int b = blockIdx.x;
    int tid = threadIdx.x;
    if (tid < T_DIM) {
        s_we[tid] = g_we[b * T_DIM + tid];
        s_ve[tid] = ve_w[tid];
    }
    __syncthreads();

    int n = tid;
    const float* ue = g_UeX + (size_t)b * T_DIM * N_DIM + n;
    float acc = 0.0f;
    #pragma unroll 4
    for (int s = 0; s < T_DIM; s++)
        acc += tanh_fast(s_we[s] + ue[(size_t)s * N_DIM]) * s_ve[s];
    float e = acc + ve_b[0];

    // block softmax over 256 n
    red[tid] = e;
    __syncthreads();
    for (int o = 128; o >= 32; o >>= 1) {
        if (tid < o) red[tid] = fmaxf(red[tid], red[tid + o]);
        __syncthreads();
    }
    if (tid < 32) {
        float v = red[tid];
        #pragma unroll
        for (int o = 16; o; o >>= 1) v = fmaxf(v, __shfl_xor_sync(0xffffffffu, v, o));
        red[tid] = v;
    }
    __syncthreads();
    float mx = red[0];
    __syncthreads();
    float ev = __expf(e - mx);
    red[tid] = ev;
    __syncthreads();
    for (int o = 128; o >= 32; o >>= 1) {
        if (tid < o) red[tid] += red[tid + o];
        __syncthreads();
    }
    if (tid < 32) {
        float v = red[tid];
        #pragma unroll
        for (int o = 16; o; o >>= 1) v += __shfl_xor_sync(0xffffffffu, v, o);
        red[tid] = v;
    }
    __syncthreads();
    float alpha = ev / red[0];
    g_xt[b * N_DIM + n] = alpha * x[(size_t)t * B_DIM * N_DIM + b * N_DIM + n];
}

// ---------------- gates = [x_tilde|h] @ [Wih|Whh]^T + b_ih + b_hh ----------------
__global__ void __launch_bounds__(256) k_gates(
        const float* __restrict__ Wih, const float* __restrict__ Whh,
        const float* __restrict__ b_ih, const float* __restrict__ b_hh) {
    __shared__ float As[16][68];
    __shared__ float Bs[16][68];
    int cb = blockIdx.x, rb = blockIdx.y;
    int tid = threadIdx.x;
    int tx = tid & 15, ty = tid >> 4;
    int kl = tid & 15, il = tid >> 4;
    int row0 = rb * 64, col0 = cb * 64;
    float acc[4][4] = {};
    for (int k0 = 0; k0 < K_GATES; k0 += 16) {
        int k = k0 + kl;
        #pragma unroll
        for (int s = 0; s < 4; s++) {
            int i = il + s * 16;
            int row = row0 + i;
            As[kl][i] = (k < N_DIM) ? g_xt[row * N_DIM + k] : g_h[row * M_DIM + (k - N_DIM)];
            int j = col0 + i;
            Bs[kl][i] = (k < N_DIM) ? Wih[j * N_DIM + k] : Whh[j * M_DIM + (k - N_DIM)];
        }
        __syncthreads();
        #pragma unroll
        for (int kk = 0; kk < 16; kk++) {
            float4 a4 = *(const float4*)&As[kk][ty * 4];
            float4 b4 = *(const float4*)&Bs[kk][tx * 4];
            float av[4] = {a4.x, a4.y, a4.z, a4.w};
            float bv[4] = {b4.x, b4.y, b4.z, b4.w};
            #pragma unroll
            for (int ii = 0; ii < 4; ii++)
                #pragma unroll
                for (int jj = 0; jj < 4; jj++) acc[ii][jj] += av[ii] * bv[jj];
        }
        __syncthreads();
    }
    #pragma unroll
    for (int ii = 0; ii < 4; ii++) {
        int row = row0 + ty * 4 + ii;
        #pragma unroll
        for (int jj = 0; jj < 4; jj++) {
            int j = col0 + tx * 4 + jj;
            g_gates[row * G_DIM + j] = acc[ii][jj] + b_ih[j] + b_hh[j];
        }
    }
}

// ---------------- final cell for t=127 (only hseq needed) ----------------
__global__ void k_cell_last() {
    int b = blockIdx.x;
    int m = threadIdx.x;
    const float* gr = g_gates + b * G_DIM;
    float si = sigmoid_fast(gr[m]);
    float sf = sigmoid_fast(gr[M_DIM + m]);
    float tg = tanh_fast(gr[2 * M_DIM + m]);
    float so = sigmoid_fast(gr[3 * M_DIM + m]);
    float cn = sf * g_c[b * M_DIM + m] + si * tg;
    float hn = so * tanh_fast(cn);
    g_hseq[(size_t)(T_DIM - 1) * B_DIM * M_DIM + b * M_DIM + m] = hn;
}

// ---------------- k_ud: partial[row][cb] = sum_j tanh(H@Ud^T + Ud_b)*vd ----------------
__global__ void __launch_bounds__(256) k_ud(
        const float* __restrict__ Ud_w, const float* __restrict__ Ud_b,
        const float* __restrict__ vd_w) {
    __shared__ float As[16][68];
    __shared__ float Bs[16][68];
    int cb = blockIdx.x, rb = blockIdx.y;
    int tid = threadIdx.x;
    int tx = tid & 15, ty = tid >> 4;
    int kl = tid & 15, il = tid >> 4;
    int row0 = rb * 64, col0 = cb * 64;
    float acc[4][4] = {};
    for (int k0 = 0; k0 < M_DIM; k0 += 16) {
        int k = k0 + kl;
        #pragma unroll
        for (int s = 0; s < 4; s++) {
            int i = il + s * 16;
            As[kl][i] = g_hseq[(size_t)(row0 + i) * M_DIM + k];
            Bs[kl][i] = Ud_w[(col0 + i) * M_DIM + k];
        }
        __syncthreads();
        #pragma unroll
        for (int kk = 0; kk < 16; kk++) {
            float4 a4 = *(const float4*)&As[kk][ty * 4];
            float4 b4 = *(const float4*)&Bs[kk][tx * 4];
            float av[4] = {a4.x, a4.y, a4.z, a4.w};
            float bv[4] = {b4.x, b4.y, b4.z, b4.w};
            #pragma unroll
            for (int ii = 0; ii < 4; ii++)
                #pragma unroll
                for (int jj = 0; jj < 4; jj++) acc[ii][jj] += av[ii] * bv[jj];
        }
        __syncthreads();
    }
    // epilogue: tanh*vd, row-sum across jj then across tx (16 lanes)
    #pragma unroll
    for (int ii = 0; ii < 4; ii++) {
        int row = row0 + ty * 4 + ii;
        float rs = 0.0f;
        #pragma unroll
        for (int jj = 0; jj < 4; jj++) {
            int j = col0 + tx * 4 + jj;
            rs += tanh_fast(acc[ii][jj] + Ud_b[j]) * vd_w[j];
        }
        #pragma unroll
        for (int o = 8; o; o >>= 1) rs += __shfl_xor_sync(0xffffffffu, rs, o);
        if (tx == 0) g_part[(size_t)row * 8 + cb] = rs;
    }
}

// ---------------- reduce 8 partials -> l[b][t] ----------------
__global__ void k_lred(const float* __restrict__ vd_b) {
    int r = blockIdx.x * 256 + threadIdx.x;   // r = t*B + b
    const float4* p = (const float4*)(g_part + (size_t)r * 8);
    float4 a = p[0], bq = p[1];
    float tot = a.x + a.y + a.z + a.w + bq.x + bq.y + bq.z + bq.w + vd_b[0];
    int tt = r >> 9;
    int b = r & 511;
    g_l[b * T_DIM + tt] = tot;
}

// ---------------- beta = softmax_t(l) -> out[512 + b*128 + t] ----------------
__global__ void k_beta(float* __restrict__ out) {
    __shared__ float red[128];
    int b = blockIdx.x;
    int tid = threadIdx.x;  // 128
    float v = g_l[b * T_DIM + tid];
    red[tid] = v;
    __syncthreads();
    for (int o = 64; o; o >>= 1) { if (tid < o) red[tid] = fmaxf(red[tid], red[tid + o]); __syncthreads(); }
    float mx = red[0];
    __syncthreads();
    float e = __expf(v - mx);
    red[tid] = e;
    __syncthreads();
    for (int o = 64; o; o >>= 1) { if (tid < o) red[tid] += red[tid + o]; __syncthreads(); }
    out[B_DIM + b * T_DIM + tid] = e / red[0];
}

// ---------------- ctx + logits fused ----------------
__global__ void k_out(float* __restrict__ out, const float* __restrict__ out_w,
                      const float* __restrict__ out_b) {
    __shared__ float s_beta[T_DIM];
    __shared__ float red[512];
    int b = blockIdx.x;
    int tid = threadIdx.x;  // 512
    if (tid < T_DIM) s_beta[tid] = out[B_DIM + b * T_DIM + tid];
    __syncthreads();
    float acc = 0.0f;
    #pragma unroll 4
    for (int tt = 0; tt < T_DIM; tt++)
        acc += s_beta[tt] * g_hseq[(size_t)tt * B_DIM * M_DIM + b * M_DIM + tid];
    red[tid] = acc * out_w[tid];
    __syncthreads();
    for (int o = 256; o; o >>= 1) { if (tid < o) red[tid] += red[tid + o]; __syncthreads(); }
    if (tid == 0) out[b] = red[0] + out_b[0];
}

// ---------------- host launcher ----------------
extern "C" void kernel_launch(void* const* d_in, const int* in_sizes, int n_in,
                              void* d_out, int out_size) {
    const float* x    = (const float*)d_in[0];
    const float* h0   = (const float*)d_in[1];
    const float* c0   = (const float*)d_in[2];
    const float* Wih  = (const float*)d_in[3];
    const float* Whh  = (const float*)d_in[4];
    const float* b_ih = (const float*)d_in[5];
    const float* b_hh = (const float*)d_in[6];
    const float* We_w = (const float*)d_in[7];
    const float* We_b = (const float*)d_in[8];
    const float* Ue_w = (const float*)d_in[9];
    const float* Ue_b = (const float*)d_in[10];
    const float* ve_w = (const float*)d_in[11];
    const float* ve_b = (const float*)d_in[12];
    const float* Ud_w = (const float*)d_in[13];
    const float* Ud_b = (const float*)d_in[14];
    const float* vd_w = (const float*)d_in[15];
    const float* vd_b = (const float*)d_in[16];
    const float* out_w = (const float*)d_in[17];
    const float* out_b = (const float*)d_in[18];
    float* out = (float*)d_out;

    k_init<<<B_DIM, M_DIM>>>(h0, c0);
    k_ue<<<dim3(B_DIM, N_DIM / 64), 256>>>(x, Ue_w, Ue_b);
    for (int t = 0; t < T_DIM; t++) {
        k_we<<<B_DIM / 4, 256>>>(t, We_w, We_b);
        k_e<<<B_DIM, 256>>>(t, x, ve_w, ve_b);
        k_gates<<<dim3(G_DIM / 64, B_DIM / 64), 256>>>(Wih, Whh, b_ih, b_hh);
    }
    k_cell_last<<<B_DIM, M_DIM>>>();
    k_ud<<<dim3(M_DIM / 64, (T_DIM * B_DIM) / 64), 256>>>(Ud_w, Ud_b, vd_w);
    k_lred<<<(T_DIM * B_DIM) / 256, 256>>>(vd_b);
    k_beta<<<B_DIM, T_DIM>>>(out);
    k_out<<<B_DIM, M_DIM>>>(out, out_w, out_b);
}

// round 3
// speedup vs baseline: 2.2848x; 2.0186x over previous
#include <cuda_runtime.h>
#include <cuda_bf16.h>
#include <math.h>

#define T_DIM 128
#define B_DIM 512
#define N_DIM 256
#define M_DIM 512
#define G_DIM 2048   // 4*M
#define K_GATES 768  // N + M
#define KSPLIT 8

// ---------------- device scratch (no allocation allowed) ----------------
__device__ float g_UeX[B_DIM * T_DIM * N_DIM];      // [b][s][n]  67 MB
__device__ float g_h[B_DIM * M_DIM];
__device__ float g_c[B_DIM * M_DIM];
__device__ float g_hseq[T_DIM * B_DIM * M_DIM];     // 134 MB
__device__ float g_xt[B_DIM * N_DIM];               // x_tilde
__device__ float g_gates[B_DIM * G_DIM];            // 4 MB
__device__ float g_wepart[KSPLIT * B_DIM * T_DIM];  // split-K partials for we (2 MB)
__device__ float g_part[(T_DIM * B_DIM) * 8];       // per-colblock row sums (2 MB)
__device__ float g_l[B_DIM * T_DIM];                // attention logits l

// ---------------- fast math helpers ----------------
__device__ __forceinline__ float tanh_fast(float x) {
    float y;
    asm("tanh.approx.f32 %0, %1;" : "=f"(y) : "f"(x));
    return y;
}
__device__ __forceinline__ float sigmoid_fast(float x) {
    return 0.5f * tanh_fast(0.5f * x) + 0.5f;
}

// ---------------- init h,c ----------------
__global__ void k_init(const float* __restrict__ h0, const float* __restrict__ c0) {
    int idx = blockIdx.x * blockDim.x + threadIdx.x;
    g_h[idx] = h0[idx];
    g_c[idx] = c0[idx];
}

// ---------------- Ue_x[b][s][n] = sum_t x[t,b,n]*Ue_w[s,t] + Ue_b[s] ----------------
__global__ void k_ue(const float* __restrict__ x, const float* __restrict__ Ue_w,
                     const float* __restrict__ Ue_b) {
    __shared__ float xs[T_DIM][64];
    int b = blockIdx.x;
    int n0 = blockIdx.y * 64;
    int tid = threadIdx.x;
    for (int idx = tid; idx < T_DIM * 64; idx += 256) {
        int t = idx >> 6, n = idx & 63;
        xs[t][n] = x[(size_t)t * B_DIM * N_DIM + b * N_DIM + n0 + n];
    }
    __syncthreads();
    for (int r = 0; r < 32; r++) {
        int o = tid + 256 * r;
        int s = o >> 6, n = o & 63;
        float acc = Ue_b[s];
        const float* uw = Ue_w + s * T_DIM;
        #pragma unroll 8
        for (int t = 0; t < T_DIM; t++) acc += xs[t][n] * uw[t];
        g_UeX[(b * T_DIM + s) * N_DIM + n0 + n] = acc;
    }
}

// ---------------- LSTM cell for step t: consumes g_gates, updates h,c,hseq[t] ----
__global__ void k_cell(int t) {
    int b = blockIdx.x;
    int m = threadIdx.x;
    const float* gr = g_gates + b * G_DIM;
    float si = sigmoid_fast(gr[m]);
    float sf = sigmoid_fast(gr[M_DIM + m]);
    float tg = tanh_fast(gr[2 * M_DIM + m]);
    float so = sigmoid_fast(gr[3 * M_DIM + m]);
    float cn = sf * g_c[b * M_DIM + m] + si * tg;
    float hn = so * tanh_fast(cn);
    g_c[b * M_DIM + m] = cn;
    g_h[b * M_DIM + m] = hn;
    g_hseq[(size_t)t * B_DIM * M_DIM + b * M_DIM + m] = hn;
}

// ---------------- k_we: split-K GEMM partials for we = [h|c] @ We_w^T --------------
// C[512,128], K=1024 split into 8 x 128. grid (2, 8, 8): 64x64 tile, 4x4 micro.
__global__ void __launch_bounds__(256) k_we(const float* __restrict__ We_w) {
    __shared__ float As[16][68];
    __shared__ float Bs[16][68];
    int cb = blockIdx.x, rb = blockIdx.y, kc = blockIdx.z;
    int tid = threadIdx.x;
    int tx = tid & 15, ty = tid >> 4;
    int kl = tid & 15, il = tid >> 4;
    int row0 = rb * 64, col0 = cb * 64;
    // k-slice [kc*128, kc*128+128): kc<4 -> g_h cols, else g_c cols
    const float* src = (kc < 4) ? (g_h + kc * 128) : (g_c + (kc - 4) * 128);
    const float* wsrc = We_w + kc * 128;
    float acc[4][4] = {};
    for (int k0 = 0; k0 < 128; k0 += 16) {
        int k = k0 + kl;
        #pragma unroll
        for (int s = 0; s < 4; s++) {
            int i = il + s * 16;
            As[kl][i] = src[(size_t)(row0 + i) * M_DIM + k];
            Bs[kl][i] = wsrc[(size_t)(col0 + i) * 1024 + k];
        }
        __syncthreads();
        #pragma unroll
        for (int kk = 0; kk < 16; kk++) {
            float4 a4 = *(const float4*)&As[kk][ty * 4];
            float4 b4 = *(const float4*)&Bs[kk][tx * 4];
            float av[4] = {a4.x, a4.y, a4.z, a4.w};
            float bv[4] = {b4.x, b4.y, b4.z, b4.w};
            #pragma unroll
            for (int ii = 0; ii < 4; ii++)
                #pragma unroll
                for (int jj = 0; jj < 4; jj++) acc[ii][jj] += av[ii] * bv[jj];
        }
        __syncthreads();
    }
    #pragma unroll
    for (int ii = 0; ii < 4; ii++) {
        int row = row0 + ty * 4 + ii;
        #pragma unroll
        for (int jj = 0; jj < 4; jj++) {
            int s = col0 + tx * 4 + jj;
            g_wepart[(kc * B_DIM + row) * T_DIM + s] = acc[ii][jj];
        }
    }
}

// ---------------- k_e: e -> softmax -> x_tilde. grid 512 (1 batch/block), 256 thr ----
__global__ void k_e(int t, const float* __restrict__ x,
                    const float* __restrict__ We_b,
                    const float* __restrict__ ve_w, const float* __restrict__ ve_b) {
    __shared__ float s_we[T_DIM];
    __shared__ float s_ve[T_DIM];
    __shared__ float red[256];
    int b = blockIdx.x;
    int tid = threadIdx.x;
    if (tid < T_DIM) {
        float w = We_b[tid];
        #pragma unroll
        for (int kc = 0; kc < KSPLIT; kc++)
            w += g_wepart[(kc * B_DIM + b) * T_DIM + tid];
        s_we[tid] = w;
        s_ve[tid] = ve_w[tid];
    }
    __syncthreads();

    int n = tid;
    const float* ue = g_UeX + (size_t)b * T_DIM * N_DIM + n;
    float acc = 0.0f;
    // explicit 8-deep load batching for MLP
    #pragma unroll
    for (int s0 = 0; s0 < T_DIM; s0 += 8) {
        float v[8];
        #pragma unroll
        for (int u = 0; u < 8; u++) v[u] = ue[(size_t)(s0 + u) * N_DIM];
        #pragma unroll
        for (int u = 0; u < 8; u++) acc += tanh_fast(s_we[s0 + u] + v[u]) * s_ve[s0 + u];
    }
    float e = acc + ve_b[0];

    // block softmax over 256 n
    red[tid] = e;
    __syncthreads();
    for (int o = 128; o >= 32; o >>= 1) {
        if (tid < o) red[tid] = fmaxf(red[tid], red[tid + o]);
        __syncthreads();
    }
    if (tid < 32) {
        float v = red[tid];
        #pragma unroll
        for (int o = 16; o; o >>= 1) v = fmaxf(v, __shfl_xor_sync(0xffffffffu, v, o));
        red[tid] = v;
    }
    __syncthreads();
    float mx = red[0];
    __syncthreads();
    float ev = __expf(e - mx);
    red[tid] = ev;
    __syncthreads();
    for (int o = 128; o >= 32; o >>= 1) {
        if (tid < o) red[tid] += red[tid + o];
        __syncthreads();
    }
    if (tid < 32) {
        float v = red[tid];
        #pragma unroll
        for (int o = 16; o; o >>= 1) v += __shfl_xor_sync(0xffffffffu, v, o);
        red[tid] = v;
    }
    __syncthreads();
    float alpha = ev / red[0];
    g_xt[b * N_DIM + n] = alpha * x[(size_t)t * B_DIM * N_DIM + b * N_DIM + n];
}

// ---------------- gates = [x_tilde|h] @ [Wih|Whh]^T + b_ih + b_hh ----------------
__global__ void __launch_bounds__(256) k_gates(
        const float* __restrict__ Wih, const float* __restrict__ Whh,
        const float* __restrict__ b_ih, const float* __restrict__ b_hh) {
    __shared__ float As[16][68];
    __shared__ float Bs[16][68];
    int cb = blockIdx.x, rb = blockIdx.y;
    int tid = threadIdx.x;
    int tx = tid & 15, ty = tid >> 4;
    int kl = tid & 15, il = tid >> 4;
    int row0 = rb * 64, col0 = cb * 64;
    float acc[4][4] = {};
    for (int k0 = 0; k0 < K_GATES; k0 += 16) {
        int k = k0 + kl;
        #pragma unroll
        for (int s = 0; s < 4; s++) {
            int i = il + s * 16;
            int row = row0 + i;
            As[kl][i] = (k < N_DIM) ? g_xt[row * N_DIM + k] : g_h[row * M_DIM + (k - N_DIM)];
            int j = col0 + i;
            Bs[kl][i] = (k < N_DIM) ? Wih[j * N_DIM + k] : Whh[j * M_DIM + (k - N_DIM)];
        }
        __syncthreads();
        #pragma unroll
        for (int kk = 0; kk < 16; kk++) {
            float4 a4 = *(const float4*)&As[kk][ty * 4];
            float4 b4 = *(const float4*)&Bs[kk][tx * 4];
            float av[4] = {a4.x, a4.y, a4.z, a4.w};
            float bv[4] = {b4.x, b4.y, b4.z, b4.w};
            #pragma unroll
            for (int ii = 0; ii < 4; ii++)
                #pragma unroll
                for (int jj = 0; jj < 4; jj++) acc[ii][jj] += av[ii] * bv[jj];
        }
        __syncthreads();
    }
    #pragma unroll
    for (int ii = 0; ii < 4; ii++) {
        int row = row0 + ty * 4 + ii;
        #pragma unroll
        for (int jj = 0; jj < 4; jj++) {
            int j = col0 + tx * 4 + jj;
            g_gates[row * G_DIM + j] = acc[ii][jj] + b_ih[j] + b_hh[j];
        }
    }
}

// ---------------- k_ud: partial[row][cb] = sum_j tanh(H@Ud^T + Ud_b)*vd ----------------
__global__ void __launch_bounds__(256) k_ud(
        const float* __restrict__ Ud_w, const float* __restrict__ Ud_b,
        const float* __restrict__ vd_w) {
    __shared__ float As[16][68];
    __shared__ float Bs[16][68];
    int cb = blockIdx.x, rb = blockIdx.y;
    int tid = threadIdx.x;
    int tx = tid & 15, ty = tid >> 4;
    int kl = tid & 15, il = tid >> 4;
    int row0 = rb * 64, col0 = cb * 64;
    float acc[4][4] = {};
    for (int k0 = 0; k0 < M_DIM; k0 += 16) {
        int k = k0 + kl;
        #pragma unroll
        for (int s = 0; s < 4; s++) {
            int i = il + s * 16;
            As[kl][i] = g_hseq[(size_t)(row0 + i) * M_DIM + k];
            Bs[kl][i] = Ud_w[(col0 + i) * M_DIM + k];
        }
        __syncthreads();
        #pragma unroll
        for (int kk = 0; kk < 16; kk++) {
            float4 a4 = *(const float4*)&As[kk][ty * 4];
            float4 b4 = *(const float4*)&Bs[kk][tx * 4];
            float av[4] = {a4.x, a4.y, a4.z, a4.w};
            float bv[4] = {b4.x, b4.y, b4.z, b4.w};
            #pragma unroll
            for (int ii = 0; ii < 4; ii++)
                #pragma unroll
                for (int jj = 0; jj < 4; jj++) acc[ii][jj] += av[ii] * bv[jj];
        }
        __syncthreads();
    }
    #pragma unroll
    for (int ii = 0; ii < 4; ii++) {
        int row = row0 + ty * 4 + ii;
        float rs = 0.0f;
        #pragma unroll
        for (int jj = 0; jj < 4; jj++) {
            int j = col0 + tx * 4 + jj;
            rs += tanh_fast(acc[ii][jj] + Ud_b[j]) * vd_w[j];
        }
        #pragma unroll
        for (int o = 8; o; o >>= 1) rs += __shfl_xor_sync(0xffffffffu, rs, o);
        if (tx == 0) g_part[(size_t)row * 8 + cb] = rs;
    }
}

// ---------------- reduce 8 partials -> l[b][t] ----------------
__global__ void k_lred(const float* __restrict__ vd_b) {
    int r = blockIdx.x * 256 + threadIdx.x;   // r = t*B + b
    const float4* p = (const float4*)(g_part + (size_t)r * 8);
    float4 a = p[0], bq = p[1];
    float tot = a.x + a.y + a.z + a.w + bq.x + bq.y + bq.z + bq.w + vd_b[0];
    int tt = r >> 9;
    int b = r & 511;
    g_l[b * T_DIM + tt] = tot;
}

// ---------------- beta = softmax_t(l) -> out[512 + b*128 + t] ----------------
__global__ void k_beta(float* __restrict__ out) {
    __shared__ float red[128];
    int b = blockIdx.x;
    int tid = threadIdx.x;  // 128
    float v = g_l[b * T_DIM + tid];
    red[tid] = v;
    __syncthreads();
    for (int o = 64; o; o >>= 1) { if (tid < o) red[tid] = fmaxf(red[tid], red[tid + o]); __syncthreads(); }
    float mx = red[0];
    __syncthreads();
    float e = __expf(v - mx);
    red[tid] = e;
    __syncthreads();
    for (int o = 64; o; o >>= 1) { if (tid < o) red[tid] += red[tid + o]; __syncthreads(); }
    out[B_DIM + b * T_DIM + tid] = e / red[0];
}

// ---------------- ctx + logits fused ----------------
__global__ void k_out(float* __restrict__ out, const float* __restrict__ out_w,
                      const float* __restrict__ out_b) {
    __shared__ float s_beta[T_DIM];
    __shared__ float red[512];
    int b = blockIdx.x;
    int tid = threadIdx.x;  // 512
    if (tid < T_DIM) s_beta[tid] = out[B_DIM + b * T_DIM + tid];
    __syncthreads();
    float acc = 0.0f;
    #pragma unroll 4
    for (int tt = 0; tt < T_DIM; tt++)
        acc += s_beta[tt] * g_hseq[(size_t)tt * B_DIM * M_DIM + b * M_DIM + tid];
    red[tid] = acc * out_w[tid];
    __syncthreads();
    for (int o = 256; o; o >>= 1) { if (tid < o) red[tid] += red[tid + o]; __syncthreads(); }
    if (tid == 0) out[b] = red[0] + out_b[0];
}

// ---------------- host launcher ----------------
extern "C" void kernel_launch(void* const* d_in, const int* in_sizes, int n_in,
                              void* d_out, int out_size) {
    const float* x    = (const float*)d_in[0];
    const float* h0   = (const float*)d_in[1];
    const float* c0   = (const float*)d_in[2];
    const float* Wih  = (const float*)d_in[3];
    const float* Whh  = (const float*)d_in[4];
    const float* b_ih = (const float*)d_in[5];
    const float* b_hh = (const float*)d_in[6];
    const float* We_w = (const float*)d_in[7];
    const float* We_b = (const float*)d_in[8];
    const float* Ue_w = (const float*)d_in[9];
    const float* Ue_b = (const float*)d_in[10];
    const float* ve_w = (const float*)d_in[11];
    const float* ve_b = (const float*)d_in[12];
    const float* Ud_w = (const float*)d_in[13];
    const float* Ud_b = (const float*)d_in[14];
    const float* vd_w = (const float*)d_in[15];
    const float* vd_b = (const float*)d_in[16];
    const float* out_w = (const float*)d_in[17];
    const float* out_b = (const float*)d_in[18];
    float* out = (float*)d_out;

    k_init<<<B_DIM, M_DIM>>>(h0, c0);
    k_ue<<<dim3(B_DIM, N_DIM / 64), 256>>>(x, Ue_w, Ue_b);
    for (int t = 0; t < T_DIM; t++) {
        if (t > 0) k_cell<<<B_DIM, M_DIM>>>(t - 1);
        k_we<<<dim3(T_DIM / 64, B_DIM / 64, KSPLIT), 256>>>(We_w);
        k_e<<<B_DIM, 256>>>(t, x, We_b, ve_w, ve_b);
        k_gates<<<dim3(G_DIM / 64, B_DIM / 64), 256>>>(Wih, Whh, b_ih, b_hh);
    }
    k_cell<<<B_DIM, M_DIM>>>(T_DIM - 1);
    k_ud<<<dim3(M_DIM / 64, (T_DIM * B_DIM) / 64), 256>>>(Ud_w, Ud_b, vd_w);
    k_lred<<<(T_DIM * B_DIM) / 256, 256>>>(vd_b);
    k_beta<<<B_DIM, T_DIM>>>(out);
    k_out<<<B_DIM, M_DIM>>>(out, out_w, out_b);
}

// round 5
// speedup vs baseline: 3.0373x; 1.3294x over previous
#include <cuda_runtime.h>
#include <cuda_bf16.h>
#include <cuda_fp16.h>
#include <cstdint>
#include <math.h>

#define T_DIM 128
#define B_DIM 512
#define N_DIM 256
#define M_DIM 512
#define G_DIM 2048   // 4*M
#define K_GATES 768  // N + M
#define KSPLIT 8
#define SPAD 36      // smem row stride (32 k + 4 pad) -> conflict-free fragments

// ---------------- device scratch (no allocation allowed) ----------------
__device__ __half g_UeX[B_DIM * T_DIM * N_DIM];     // [b][s][n]  33.5 MB (fp16)
__device__ float g_h[B_DIM * M_DIM];
__device__ float g_c[B_DIM * M_DIM];
__device__ float g_hseq[T_DIM * B_DIM * M_DIM];     // 134 MB
__device__ float g_xt[B_DIM * N_DIM];               // x_tilde
__device__ float g_gates[B_DIM * G_DIM];            // 4 MB
__device__ float g_wepart[KSPLIT * B_DIM * T_DIM];  // split-K partials for we
__device__ float g_part[(T_DIM * B_DIM) * 16];      // per-(colblock,warp) row sums (4 MB)
__device__ float g_l[B_DIM * T_DIM];                // attention logits l

// ---------------- fast math helpers ----------------
__device__ __forceinline__ float tanh_fast(float x) {
    float y;
    asm("tanh.approx.f32 %0, %1;" : "=f"(y) : "f"(x));
    return y;
}
__device__ __forceinline__ float sigmoid_fast(float x) {
    return 0.5f * tanh_fast(0.5f * x) + 0.5f;
}

// ---------------- tf32 mma helpers ----------------
__device__ __forceinline__ void tf32_split(float v, uint32_t& hi, uint32_t& lo) {
    asm("cvt.rna.tf32.f32 %0, %1;" : "=r"(hi) : "f"(v));
    float r = v - __uint_as_float(hi);
    asm("cvt.rna.tf32.f32 %0, %1;" : "=r"(lo) : "f"(r));
}
__device__ __forceinline__ void mma_tf32(float* c, const uint32_t* a, const uint32_t* b) {
    asm volatile(
        "mma.sync.aligned.m16n8k8.row.col.f32.tf32.tf32.f32 "
        "{%0,%1,%2,%3}, {%4,%5,%6,%7}, {%8,%9}, {%0,%1,%2,%3};\n"
        : "+f"(c[0]), "+f"(c[1]), "+f"(c[2]), "+f"(c[3])
        : "r"(a[0]), "r"(a[1]), "r"(a[2]), "r"(a[3]), "r"(b[0]), "r"(b[1]));
}

// ---------------- init h,c ----------------
__global__ void k_init(const float* __restrict__ h0, const float* __restrict__ c0) {
    int idx = blockIdx.x * blockDim.x + threadIdx.x;
    g_h[idx] = h0[idx];
    g_c[idx] = c0[idx];
}

// ---------------- Ue_x[b][s][n] = sum_t x[t,b,n]*Ue_w[s,t] + Ue_b[s]  (fp16 out) ----
__global__ void k_ue(const float* __restrict__ x, const float* __restrict__ Ue_w,
                     const float* __restrict__ Ue_b) {
    __shared__ float xs[T_DIM][64];
    int b = blockIdx.x;
    int n0 = blockIdx.y * 64;
    int tid = threadIdx.x;
    for (int idx = tid; idx < T_DIM * 64; idx += 256) {
        int t = idx >> 6, n = idx & 63;
        xs[t][n] = x[(size_t)t * B_DIM * N_DIM + b * N_DIM + n0 + n];
    }
    __syncthreads();
    for (int r = 0; r < 32; r++) {
        int o = tid + 256 * r;
        int s = o >> 6, n = o & 63;
        float acc = Ue_b[s];
        const float* uw = Ue_w + s * T_DIM;
        #pragma unroll 8
        for (int t = 0; t < T_DIM; t++) acc += xs[t][n] * uw[t];
        g_UeX[(b * T_DIM + s) * N_DIM + n0 + n] = __float2half_rn(acc);
    }
}

// ---------------- LSTM cell for step t ----------------
__global__ void k_cell(int t) {
    int b = blockIdx.x;
    int m = threadIdx.x;
    const float* gr = g_gates + b * G_DIM;
    float si = sigmoid_fast(gr[m]);
    float sf = sigmoid_fast(gr[M_DIM + m]);
    float tg = tanh_fast(gr[2 * M_DIM + m]);
    float so = sigmoid_fast(gr[3 * M_DIM + m]);
    float cn = sf * g_c[b * M_DIM + m] + si * tg;
    float hn = so * tanh_fast(cn);
    g_c[b * M_DIM + m] = cn;
    g_h[b * M_DIM + m] = hn;
    g_hseq[(size_t)t * B_DIM * M_DIM + b * M_DIM + m] = hn;
}

// ---------------- k_we: split-K FFMA GEMM partials for we = [h|c] @ We_w^T --------
__global__ void __launch_bounds__(256) k_we(const float* __restrict__ We_w) {
    __shared__ float As[16][68];
    __shared__ float Bs[16][68];
    int cb = blockIdx.x, rb = blockIdx.y, kc = blockIdx.z;
    int tid = threadIdx.x;
    int tx = tid & 15, ty = tid >> 4;
    int kl = tid & 15, il = tid >> 4;
    int row0 = rb * 64, col0 = cb * 64;
    const float* src = (kc < 4) ? (g_h + kc * 128) : (g_c + (kc - 4) * 128);
    const float* wsrc = We_w + kc * 128;
    float acc[4][4] = {};
    for (int k0 = 0; k0 < 128; k0 += 16) {
        int k = k0 + kl;
        #pragma unroll
        for (int s = 0; s < 4; s++) {
            int i = il + s * 16;
            As[kl][i] = src[(size_t)(row0 + i) * M_DIM + k];
            Bs[kl][i] = wsrc[(size_t)(col0 + i) * 1024 + k];
        }
        __syncthreads();
        #pragma unroll
        for (int kk = 0; kk < 16; kk++) {
            float4 a4 = *(const float4*)&As[kk][ty * 4];
            float4 b4 = *(const float4*)&Bs[kk][tx * 4];
            float av[4] = {a4.x, a4.y, a4.z, a4.w};
            float bv[4] = {b4.x, b4.y, b4.z, b4.w};
            #pragma unroll
            for (int ii = 0; ii < 4; ii++)
                #pragma unroll
                for (int jj = 0; jj < 4; jj++) acc[ii][jj] += av[ii] * bv[jj];
        }
        __syncthreads();
    }
    #pragma unroll
    for (int ii = 0; ii < 4; ii++) {
        int row = row0 + ty * 4 + ii;
        #pragma unroll
        for (int jj = 0; jj < 4; jj++) {
            int s = col0 + tx * 4 + jj;
            g_wepart[(kc * B_DIM + row) * T_DIM + s] = acc[ii][jj];
        }
    }
}

// ---------------- k_e: e -> softmax -> x_tilde. grid 512, 256 thr ----------------
__global__ void k_e(int t, const float* __restrict__ x,
                    const float* __restrict__ We_b,
                    const float* __restrict__ ve_w, const float* __restrict__ ve_b) {
    __shared__ float s_we[T_DIM];
    __shared__ float s_ve[T_DIM];
    __shared__ float red[256];
    int b = blockIdx.x;
    int tid = threadIdx.x;
    if (tid < T_DIM) {
        float w = We_b[tid];
        #pragma unroll
        for (int kc = 0; kc < KSPLIT; kc++)
            w += g_wepart[(kc * B_DIM + b) * T_DIM + tid];
        s_we[tid] = w;
        s_ve[tid] = ve_w[tid];
    }
    __syncthreads();

    int n = tid;
    const __half* ue = g_UeX + (size_t)b * T_DIM * N_DIM + n;
    float acc = 0.0f;
    #pragma unroll
    for (int s0 = 0; s0 < T_DIM; s0 += 8) {
        float v[8];
        #pragma unroll
        for (int u = 0; u < 8; u++) v[u] = __half2float(ue[(size_t)(s0 + u) * N_DIM]);
        #pragma unroll
        for (int u = 0; u < 8; u++) acc += tanh_fast(s_we[s0 + u] + v[u]) * s_ve[s0 + u];
    }
    float e = acc + ve_b[0];

    red[tid] = e;
    __syncthreads();
    for (int o = 128; o >= 32; o >>= 1) {
        if (tid < o) red[tid] = fmaxf(red[tid], red[tid + o]);
        __syncthreads();
    }
    if (tid < 32) {
        float v = red[tid];
        #pragma unroll
        for (int o = 16; o; o >>= 1) v = fmaxf(v, __shfl_xor_sync(0xffffffffu, v, o));
        red[tid] = v;
    }
    __syncthreads();
    float mx = red[0];
    __syncthreads();
    float ev = __expf(e - mx);
    red[tid] = ev;
    __syncthreads();
    for (int o = 128; o >= 32; o >>= 1) {
        if (tid < o) red[tid] += red[tid + o];
        __syncthreads();
    }
    if (tid < 32) {
        float v = red[tid];
        #pragma unroll
        for (int o = 16; o; o >>= 1) v += __shfl_xor_sync(0xffffffffu, v, o);
        red[tid] = v;
    }
    __syncthreads();
    float alpha = ev / red[0];
    g_xt[b * N_DIM + n] = alpha * x[(size_t)t * B_DIM * N_DIM + b * N_DIM + n];
}

// ---------------- k_gates (tf32 3x mma): [xt|h] @ [Wih|Whh]^T + biases ------------
// grid (32, 4): block 128m x 64n, 8 warps (4m x 2n), warp 32x32
__global__ void __launch_bounds__(256) k_gates(
        const float* __restrict__ Wih, const float* __restrict__ Whh,
        const float* __restrict__ b_ih, const float* __restrict__ b_hh) {
    __shared__ float As[128 * SPAD];
    __shared__ float Bs[64 * SPAD];
    int tid = threadIdx.x;
    int w = tid >> 5, lane = tid & 31;
    int g = lane >> 2, tig = lane & 3;
    int wm = w & 3, wn = w >> 2;
    int m0 = blockIdx.y * 128, n0 = blockIdx.x * 64;
    int r = tid >> 3, kq = (tid & 7) * 4;
    float c[2][4][4] = {};

    for (int k0 = 0; k0 < K_GATES; k0 += 32) {
        const float* asrc; int astride;
        if (k0 < N_DIM) { asrc = g_xt + k0; astride = N_DIM; }
        else            { asrc = g_h + (k0 - N_DIM); astride = M_DIM; }
        #pragma unroll
        for (int i = 0; i < 4; i++) {
            int row = r + 32 * i;
            *(float4*)&As[row * SPAD + kq] =
                *(const float4*)(asrc + (size_t)(m0 + row) * astride + kq);
        }
        const float* bsrc; int bstride;
        if (k0 < N_DIM) { bsrc = Wih + k0; bstride = N_DIM; }
        else            { bsrc = Whh + (k0 - N_DIM); bstride = M_DIM; }
        #pragma unroll
        for (int i = 0; i < 2; i++) {
            int row = r + 32 * i;
            *(float4*)&Bs[row * SPAD + kq] =
                *(const float4*)(bsrc + (size_t)(n0 + row) * bstride + kq);
        }
        __syncthreads();
        #pragma unroll
        for (int kt = 0; kt < 4; kt++) {
            int kk = kt * 8 + tig;
            uint32_t ahi[2][4], alo[2][4], bhi[4][2], blo[4][2];
            #pragma unroll
            for (int mt = 0; mt < 2; mt++) {
                int rb = wm * 32 + mt * 16 + g;
                tf32_split(As[rb * SPAD + kk],           ahi[mt][0], alo[mt][0]);
                tf32_split(As[(rb + 8) * SPAD + kk],     ahi[mt][1], alo[mt][1]);
                tf32_split(As[rb * SPAD + kk + 4],       ahi[mt][2], alo[mt][2]);
                tf32_split(As[(rb + 8) * SPAD + kk + 4], ahi[mt][3], alo[mt][3]);
            }
            #pragma unroll
            for (int nt = 0; nt < 4; nt++) {
                int nb = wn * 32 + nt * 8 + g;
                tf32_split(Bs[nb * SPAD + kk],     bhi[nt][0], blo[nt][0]);
                tf32_split(Bs[nb * SPAD + kk + 4], bhi[nt][1], blo[nt][1]);
            }
            #pragma unroll
            for (int mt = 0; mt < 2; mt++)
                #pragma unroll
                for (int nt = 0; nt < 4; nt++) {
                    mma_tf32(c[mt][nt], ahi[mt], bhi[nt]);
                    mma_tf32(c[mt][nt], ahi[mt], blo[nt]);
                    mma_tf32(c[mt][nt], alo[mt], bhi[nt]);
                }
        }
        __syncthreads();
    }
    #pragma unroll
    for (int mt = 0; mt < 2; mt++) {
        int r0 = m0 + wm * 32 + mt * 16 + g;
        #pragma unroll
        for (int nt = 0; nt < 4; nt++) {
            int j0 = n0 + wn * 32 + nt * 8 + tig * 2;
            float bb0 = b_ih[j0] + b_hh[j0];
            float bb1 = b_ih[j0 + 1] + b_hh[j0 + 1];
            g_gates[r0 * G_DIM + j0]           = c[mt][nt][0] + bb0;
            g_gates[r0 * G_DIM + j0 + 1]       = c[mt][nt][1] + bb1;
            g_gates[(r0 + 8) * G_DIM + j0]     = c[mt][nt][2] + bb0;
            g_gates[(r0 + 8) * G_DIM + j0 + 1] = c[mt][nt][3] + bb1;
        }
    }
}

// ---------------- k_ud (tf32 3x mma): partials of sum_j tanh(H@Ud^T+b)*vd ---------
// grid (8, 512): block 128m x 64n; epilogue reduces across each warp's 32 cols
__global__ void __launch_bounds__(256) k_ud(
        const float* __restrict__ Ud_w, const float* __restrict__ Ud_b,
        const float* __restrict__ vd_w) {
    __shared__ float As[128 * SPAD];
    __shared__ float Bs[64 * SPAD];
    int tid = threadIdx.x;
    int w = tid >> 5, lane = tid & 31;
    int g = lane >> 2, tig = lane & 3;
    int wm = w & 3, wn = w >> 2;
    int m0 = blockIdx.y * 128, n0 = blockIdx.x * 64;
    int r = tid >> 3, kq = (tid & 7) * 4;
    float c[2][4][4] = {};

    for (int k0 = 0; k0 < M_DIM; k0 += 32) {
        #pragma unroll
        for (int i = 0; i < 4; i++) {
            int row = r + 32 * i;
            *(float4*)&As[row * SPAD + kq] =
                *(const float4*)(g_hseq + (size_t)(m0 + row) * M_DIM + k0 + kq);
        }
        #pragma unroll
        for (int i = 0; i < 2; i++) {
            int row = r + 32 * i;
            *(float4*)&Bs[row * SPAD + kq] =
                *(const float4*)(Ud_w + (size_t)(n0 + row) * M_DIM + k0 + kq);
        }
        __syncthreads();
        #pragma unroll
        for (int kt = 0; kt < 4; kt++) {
            int kk = kt * 8 + tig;
            uint32_t ahi[2][4], alo[2][4], bhi[4][2], blo[4][2];
            #pragma unroll
            for (int mt = 0; mt < 2; mt++) {
                int rb = wm * 32 + mt * 16 + g;
                tf32_split(As[rb * SPAD + kk],           ahi[mt][0], alo[mt][0]);
                tf32_split(As[(rb + 8) * SPAD + kk],     ahi[mt][1], alo[mt][1]);
                tf32_split(As[rb * SPAD + kk + 4],       ahi[mt][2], alo[mt][2]);
                tf32_split(As[(rb + 8) * SPAD + kk + 4], ahi[mt][3], alo[mt][3]);
            }
            #pragma unroll
            for (int nt = 0; nt < 4; nt++) {
                int nb = wn * 32 + nt * 8 + g;
                tf32_split(Bs[nb * SPAD + kk],     bhi[nt][0], blo[nt][0]);
                tf32_split(Bs[nb * SPAD + kk + 4], bhi[nt][1], blo[nt][1]);
            }
            #pragma unroll
            for (int mt = 0; mt < 2; mt++)
                #pragma unroll
                for (int nt = 0; nt < 4; nt++) {
                    mma_tf32(c[mt][nt], ahi[mt], bhi[nt]);
                    mma_tf32(c[mt][nt], ahi[mt], blo[nt]);
                    mma_tf32(c[mt][nt], alo[mt], bhi[nt]);
                }
        }
        __syncthreads();
    }
    // epilogue: tanh*vd, reduce over warp's 32 cols
    #pragma unroll
    for (int mt = 0; mt < 2; mt++) {
        float rs0 = 0.0f, rs8 = 0.0f;
        #pragma unroll
        for (int nt = 0; nt < 4; nt++) {
            int j0 = n0 + wn * 32 + nt * 8 + tig * 2;
            float w0 = vd_w[j0], w1 = vd_w[j0 + 1];
            float d0 = Ud_b[j0], d1 = Ud_b[j0 + 1];
            rs0 += tanh_fast(c[mt][nt][0] + d0) * w0 + tanh_fast(c[mt][nt][1] + d1) * w1;
            rs8 += tanh_fast(c[mt][nt][2] + d0) * w0 + tanh_fast(c[mt][nt][3] + d1) * w1;
        }
        rs0 += __shfl_xor_sync(0xffffffffu, rs0, 1);
        rs0 += __shfl_xor_sync(0xffffffffu, rs0, 2);
        rs8 += __shfl_xor_sync(0xffffffffu, rs8, 1);
        rs8 += __shfl_xor_sync(0xffffffffu, rs8, 2);
        if (tig == 0) {
            int r0 = m0 + wm * 32 + mt * 16 + g;
            g_part[(size_t)r0 * 16 + blockIdx.x * 2 + wn] = rs0;
            g_part[(size_t)(r0 + 8) * 16 + blockIdx.x * 2 + wn] = rs8;
        }
    }
}

// ---------------- reduce 16 partials -> l[b][t] ----------------
__global__ void k_lred(const float* __restrict__ vd_b) {
    int r = blockIdx.x * 256 + threadIdx.x;   // r = t*B + b
    const float4* p = (const float4*)(g_part + (size_t)r * 16);
    float tot = vd_b[0];
    #pragma unroll
    for (int i = 0; i < 4; i++) {
        float4 a = p[i];
        tot += a.x + a.y + a.z + a.w;
    }
    int tt = r >> 9;
    int b = r & 511;
    g_l[b * T_DIM + tt] = tot;
}

// ---------------- beta = softmax_t(l) -> out[512 + b*128 + t] ----------------
__global__ void k_beta(float* __restrict__ out) {
    __shared__ float red[128];
    int b = blockIdx.x;
    int tid = threadIdx.x;  // 128
    float v = g_l[b * T_DIM + tid];
    red[tid] = v;
    __syncthreads();
    for (int o = 64; o; o >>= 1) { if (tid < o) red[tid] = fmaxf(red[tid], red[tid + o]); __syncthreads(); }
    float mx = red[0];
    __syncthreads();
    float e = __expf(v - mx);
    red[tid] = e;
    __syncthreads();
    for (int o = 64; o; o >>= 1) { if (tid < o) red[tid] += red[tid + o]; __syncthreads(); }
    out[B_DIM + b * T_DIM + tid] = e / red[0];
}

// ---------------- ctx + logits fused ----------------
__global__ void k_out(float* __restrict__ out, const float* __restrict__ out_w,
                      const float* __restrict__ out_b) {
    __shared__ float s_beta[T_DIM];
    __shared__ float red[512];
    int b = blockIdx.x;
    int tid = threadIdx.x;  // 512
    if (tid < T_DIM) s_beta[tid] = out[B_DIM + b * T_DIM + tid];
    __syncthreads();
    float acc = 0.0f;
    #pragma unroll 4
    for (int tt = 0; tt < T_DIM; tt++)
        acc += s_beta[tt] * g_hseq[(size_t)tt * B_DIM * M_DIM + b * M_DIM + tid];
    red[tid] = acc * out_w[tid];
    __syncthreads();
    for (int o = 256; o; o >>= 1) { if (tid < o) red[tid] += red[tid + o]; __syncthreads(); }
    if (tid == 0) out[b] = red[0] + out_b[0];
}

// ---------------- host launcher ----------------
extern "C" void kernel_launch(void* const* d_in, const int* in_sizes, int n_in,
                              void* d_out, int out_size) {
    const float* x    = (const float*)d_in[0];
    const float* h0   = (const float*)d_in[1];
    const float* c0   = (const float*)d_in[2];
    const float* Wih  = (const float*)d_in[3];
    const float* Whh  = (const float*)d_in[4];
    const float* b_ih = (const float*)d_in[5];
    const float* b_hh = (const float*)d_in[6];
    const float* We_w = (const float*)d_in[7];
    const float* We_b = (const float*)d_in[8];
    const float* Ue_w = (const float*)d_in[9];
    const float* Ue_b = (const float*)d_in[10];
    const float* ve_w = (const float*)d_in[11];
    const float* ve_b = (const float*)d_in[12];
    const float* Ud_w = (const float*)d_in[13];
    const float* Ud_b = (const float*)d_in[14];
    const float* vd_w = (const float*)d_in[15];
    const float* vd_b = (const float*)d_in[16];
    const float* out_w = (const float*)d_in[17];
    const float* out_b = (const float*)d_in[18];
    float* out = (float*)d_out;

    k_init<<<B_DIM, M_DIM>>>(h0, c0);
    k_ue<<<dim3(B_DIM, N_DIM / 64), 256>>>(x, Ue_w, Ue_b);
    for (int t = 0; t < T_DIM; t++) {
        if (t > 0) k_cell<<<B_DIM, M_DIM>>>(t - 1);
        k_we<<<dim3(T_DIM / 64, B_DIM / 64, KSPLIT), 256>>>(We_w);
        k_e<<<B_DIM, 256>>>(t, x, We_b, ve_w, ve_b);
        k_gates<<<dim3(G_DIM / 64, B_DIM / 128), 256>>>(Wih, Whh, b_ih, b_hh);
    }
    k_cell<<<B_DIM, M_DIM>>>(T_DIM - 1);
    k_ud<<<dim3(M_DIM / 64, (T_DIM * B_DIM) / 128), 256>>>(Ud_w, Ud_b, vd_w);
    k_lred<<<(T_DIM * B_DIM) / 256, 256>>>(vd_b);
    k_beta<<<B_DIM, T_DIM>>>(out);
    k_out<<<B_DIM, M_DIM>>>(out, out_w, out_b);
}